// round 16
// baseline (speedup 1.0000x reference)
#include <cuda_runtime.h>

#define NB     4
#define IN_DIM 8
#define OUT_D  64
#define N_WIN  64
#define N_SEQ  4096
#define N_REAL 6144
#define PAD    64
#define ROW    (PAD + N_REAL + 8)   // 6216 floats per (b,i) row
#define TT     512                  // t per block
#define OB     8                    // o per block (all handled by every thread)
#define XLEN   576                  // TT + N_WIN
#define XDIM   584                  // padded shared row (float4-divisible)

__device__ __align__(16) float g_X[NB][IN_DIM][ROW];

// ---------------- fused zero + scatter: one block per (b,i) row ----------------

__global__ void scatter_kernel(const float* __restrict__ x, const int* __restrict__ idx) {
    const int b = blockIdx.x >> 3;
    const int i = blockIdx.x & 7;
    float* row = g_X[b][i];
    const int tid = threadIdx.x;

    const float4 z = make_float4(0.f, 0.f, 0.f, 0.f);
    for (int j = tid; j < ROW / 4; j += 512)
        reinterpret_cast<float4*>(row)[j] = z;
    __syncthreads();

    const int*   ib = idx + b * N_SEQ;
    const float* xb = x + (size_t)(b * IN_DIM + i) * N_SEQ;
    for (int s = tid; s < N_SEQ; s += 512)
        row[PAD + ib[s]] = xb[s];
}

// ---------------- f32x2 helpers ----------------

__device__ __forceinline__ unsigned long long ffma2(unsigned long long a,
                                                    unsigned long long b,
                                                    unsigned long long c) {
    unsigned long long d;
    asm("fma.rn.f32x2 %0, %1, %2, %3;" : "=l"(d) : "l"(a), "l"(b), "l"(c));
    return d;
}
__device__ __forceinline__ unsigned long long pack2(float v) {
    unsigned long long r;
    unsigned int u = __float_as_uint(v);
    asm("mov.b64 %0, {%1, %1};" : "=l"(r) : "r"(u));
    return r;
}
__device__ __forceinline__ float2 unpack2(unsigned long long v) {
    float2 r;
    asm("mov.b64 {%0, %1}, %2;" : "=f"(r.x), "=f"(r.y) : "l"(v));
    return r;
}
__device__ __forceinline__ unsigned long long lds2(const float* p) {
    return *reinterpret_cast<const unsigned long long*>(p);
}

// ---------------- conv ----------------
// out[b,o,t] = bias[o] + sum_{i,w} W[o,i,w] * Xhat[b,i,t-w]
// Block: one b, 8 o-rows, 512 t. 2 warps; each warp owns 256 t (p=0..3
// t-pairs per lane), every thread accumulates ALL 8 o-rows -> each x LDS.64
// feeds 8 FFMA2 (LDS-per-FMA halved vs o=4). Weights pre-duplicated (w,w)
// in shared; one LDS.128 broadcast = f32x2 operands for 2 consecutive lags,
// zero packing MOVs in the hot loop (R15 lesson). sXb[j] = sXa[j+1] keeps
// odd-lag pair loads 8B-aligned.

extern __shared__ float smem[];   // [sW2: 4096 float2 = 32KB][sXa: 8*584][sXb: 8*584]

__global__ __launch_bounds__(64, 3)
void conv_kernel(const float* __restrict__ weight,
                 const float* __restrict__ bias,
                 float* __restrict__ out) {
    float2* sW2 = reinterpret_cast<float2*>(smem);     // [o][i*64+w] dup pairs
    float*  sXa = smem + 8192;
    float*  sXb = sXa + IN_DIM * XDIM;

    const int tid    = threadIdx.x;
    const int warp   = tid >> 5;
    const int lane   = tid & 31;
    const int T0     = blockIdx.x * TT;
    const int o_base = blockIdx.y * OB;
    const int b      = blockIdx.z;

    // Weights: 8 rows x 512 floats (contiguous), duplicated to (v,v) pairs.
    {
        const float4* wg = reinterpret_cast<const float4*>(weight + (size_t)o_base * 512);
        float4* ws = reinterpret_cast<float4*>(sW2);
#pragma unroll
        for (int r = 0; r < 16; ++r) {
            const int f4 = tid + r * 64;         // 0..1023
            float4 v = wg[f4];
            ws[f4 * 2 + 0] = make_float4(v.x, v.x, v.y, v.y);
            ws[f4 * 2 + 1] = make_float4(v.z, v.z, v.w, v.w);
        }
    }
    // X tile: sXa[i][j] = Xhat[b][i][T0-64+j]; sXb = shifted by 1 (float4 path)
#pragma unroll
    for (int i = 0; i < IN_DIM; ++i) {
        const float4* gx4 = reinterpret_cast<const float4*>(&g_X[b][i][T0]);
        float4* xa4 = reinterpret_cast<float4*>(sXa + i * XDIM);
        float4* xb4 = reinterpret_cast<float4*>(sXb + i * XDIM);
#pragma unroll
        for (int r = 0; r < 3; ++r) {
            const int k = tid + r * 64;          // 0..191, need k<144
            if (k < XLEN / 4) {
                float4 a = gx4[k];
                float4 c = gx4[k + 1];           // tail pad keeps this in-bounds
                xa4[k] = a;
                xb4[k] = make_float4(a.y, a.z, a.w, c.x);
            }
        }
    }
    __syncthreads();

    const int wt = warp * 256;
    const int tl = lane * 2;

    unsigned long long acc[OB][4];
#pragma unroll
    for (int oo = 0; oo < OB; ++oo) {
        const unsigned long long bz = pack2(__ldg(&bias[o_base + oo]));
#pragma unroll
        for (int p = 0; p < 4; ++p) acc[oo][p] = bz;
    }

#pragma unroll 1
    for (int i = 0; i < IN_DIM; ++i) {
        const float*  xa = sXa + i * XDIM + wt + tl + 64;   // even lag pairs
        const float*  xb = sXb + i * XDIM + wt + tl + 62;   // odd  lag pairs
        const float2* wr = sW2 + i * 64;                    // + oo*512
#pragma unroll 4
        for (int w2 = 0; w2 < N_WIN; w2 += 2) {
            unsigned long long xe[4], xo[4];
#pragma unroll
            for (int p = 0; p < 4; ++p) xe[p] = lds2(xa + p * 64 - w2);
#pragma unroll
            for (int p = 0; p < 4; ++p) xo[p] = lds2(xb + p * 64 - w2);
#pragma unroll
            for (int oo = 0; oo < OB; ++oo) {
                ulonglong2 q = *reinterpret_cast<const ulonglong2*>(&wr[oo * 512 + w2]);
#pragma unroll
                for (int p = 0; p < 4; ++p)
                    acc[oo][p] = ffma2(q.x, xe[p], acc[oo][p]);
#pragma unroll
                for (int p = 0; p < 4; ++p)
                    acc[oo][p] = ffma2(q.y, xo[p], acc[oo][p]);
            }
        }
    }

    // Epilogue: bias already in acc; coalesced float2 stores
#pragma unroll
    for (int oo = 0; oo < OB; ++oo) {
        const int o = o_base + oo;
        float* op = out + ((size_t)(b * OUT_D + o)) * N_REAL + T0 + wt + tl;
#pragma unroll
        for (int p = 0; p < 4; ++p)
            reinterpret_cast<float2*>(op)[p * 32] = unpack2(acc[oo][p]);
    }
}

// ---------------- launch ----------------

extern "C" void kernel_launch(void* const* d_in, const int* in_sizes, int n_in,
                              void* d_out, int out_size) {
    (void)in_sizes; (void)n_in; (void)out_size;
    const float* x      = (const float*)d_in[0];   // (B, IN_DIM, N_SEQ)
    const float* weight = (const float*)d_in[1];   // (OUT_D, IN_DIM, N_WIN)
    const float* bias   = (const float*)d_in[2];   // (OUT_D)
    const int*   idx    = (const int*)  d_in[3];   // (B, N_SEQ)
    float* out = (float*)d_out;                    // (B, OUT_D, N_REAL)

    const size_t shbytes = 4096 * sizeof(float2) + 2 * IN_DIM * XDIM * sizeof(float); // 70144
    cudaFuncSetAttribute(conv_kernel, cudaFuncAttributeMaxDynamicSharedMemorySize, (int)shbytes);

    scatter_kernel<<<NB * IN_DIM, 512>>>(x, idx);

    dim3 grid(N_REAL / TT, OUT_D / OB, NB);        // (12, 8, 4) = 384 blocks
    conv_kernel<<<grid, 64, shbytes>>>(weight, bias, out);
}